// round 14
// baseline (speedup 1.0000x reference)
#include <cuda_runtime.h>
#include <cooperative_groups.h>
#include <cstdint>
#include <math.h>

namespace cg = cooperative_groups;

#define BLOCK 512
#define CLUSTER 8
#define CAP 12

// shared-memory layout (floats). Per CTA: 4 heads, 32 e-columns.
#define OFF_X0    0        // 1024  X buffer A: [d 0..255][4 h]
#define OFF_X1    1024     // 1024  X buffer B
#define OFF_SCAL  2048     // 96    per-stage column scales [3][32]
#define OFF_CNT   2144     // 32    per-column bucket count (int)
#define OFF_COLK  2176     // 384   bucket packed (k<<8|d7) (int) [32][CAP]
#define OFF_COLC6 2560     // 384   bucket c6 (int) [32][CAP]
#define OFF_COLCV 2944     // 1152  correction values [3][32][CAP]
#define OFF_P4T   4096     // 256   p4 row for b
#define OFF_P11T  4352     // 256   p11 row for b
#define OFF_P14T  4608     // 256   p14 row for b
#define OFF_P1T   4864     // 8192  p1 slice [256 d][32 e]; becomes M in stage 0
#define OFF_P3T   13056    // 8192  p3 slice [256 d][32 e]
#define OFF_RED   21248    // 2048  partials [16 dch][4 h][32 e]
#define SMEM_FLOATS 23296
#define SMEM_BYTES (SMEM_FLOATS * 4)   // 93,184 B

extern __shared__ float smem[];

__device__ __forceinline__ void cp_async16(uint32_t saddr, const void* gptr) {
    asm volatile("cp.async.cg.shared.global [%0], [%1], 16;\n"
                 :: "r"(saddr), "l"(gptr));
}

__global__ void __cluster_dims__(CLUSTER, 1, 1) __launch_bounds__(BLOCK, 1)
chain_kernel(const float* __restrict__ p1, const float* __restrict__ p2,
             const float* __restrict__ p3, const float* __restrict__ p4,
             const int* __restrict__ p5, const int* __restrict__ p6,
             const int* __restrict__ p7, const int* __restrict__ p8,
             const float* __restrict__ p9, const float* __restrict__ p10,
             const float* __restrict__ p11, const float* __restrict__ p12,
             const float* __restrict__ p13, const float* __restrict__ p14,
             const float* __restrict__ p15, const float* __restrict__ p16,
             float* __restrict__ out, int K)
{
    cg::cluster_group cluster = cg::this_cluster();
    const int tid  = (int)threadIdx.x;
    const int rank = (int)cluster.block_rank();   // e-segment 0..7
    const int cid  = (int)blockIdx.x >> 3;        // 0..17
    const int b    = cid / 3;                     // batch 0..5
    const int h0   = (cid % 3) * 4;               // head-group base
    const int e0   = rank * 32;

    float* X0     = smem + OFF_X0;
    float* X1     = smem + OFF_X1;
    float* scal   = smem + OFF_SCAL;
    float* colcv  = smem + OFF_COLCV;
    float* p1t    = smem + OFF_P1T;
    float* p3t    = smem + OFF_P3T;
    float* red    = smem + OFF_RED;
    int*   colcnt = (int*)(smem + OFF_CNT);
    int*   colk   = (int*)(smem + OFF_COLK);
    int*   colc6  = (int*)(smem + OFF_COLC6);

    const int KC = (K < 2048) ? K : 2048;

    // ---- A: cp.async burst: p1/p3 slices + gather rows ----
    {
        uint32_t sb = (uint32_t)__cvta_generic_to_shared(smem);
        const float* g1 = p1 + b * 65536 + e0;
        const float* g3 = p3 + b * 65536 + e0;
        #pragma unroll
        for (int it = 0; it < 4; it++) {
            int idx = tid + it * BLOCK;
            int row = idx >> 3, q = (idx & 7) << 2;
            cp_async16(sb + (OFF_P1T + row * 32 + q) * 4, g1 + row * 256 + q);
            cp_async16(sb + (OFF_P3T + row * 32 + q) * 4, g3 + row * 256 + q);
        }
        if (tid < 192) {
            int a = tid / 64, c = (tid % 64) << 2;
            const float* gs = (a == 0) ? p4 : (a == 1) ? p11 : p14;
            cp_async16(sb + (OFF_P4T + a * 256 + c) * 4, gs + b * 256 + c);
        }
        asm volatile("cp.async.commit_group;\n" ::: "memory");
    }

    // ---- B: counters, X0 transpose-load (4 heads), mod scales ----
    if (tid < 32) colcnt[tid] = 0;

    for (int i = tid; i < 1024; i += BLOCK) {     // 2 iters
        int h = i >> 8, d = i & 255;
        X0[d * 4 + h] = p2[(h0 + h) * 1536 + b * 256 + d];
    }

    if (tid < 32) {
        float fr[3] = { p9[0],  p12[0], p15[0] };
        float ph[3] = { p10[0], p13[0], p16[0] };
        float t = (float)(e0 + tid);
        #pragma unroll
        for (int s = 0; s < 3; s++) {
            float a  = t * 6.2831853071795864f;
            a = a * fr[s] + ph[s];
            float sv = sinf(a);
            float m  = sv * sv * 0.1f + 0.95f;
            scal[s * 32 + tid] = (s == 1) ? m : (1.0f / m);
        }
    }
    __syncthreads();   // counters + X0 visible before scan

    // ---- C: scan from GLOBAL -> per-column buckets ----
    #pragma unroll
    for (int it = 0; it < 4; it++) {
        int k = tid + it * BLOCK;
        if (k < KC && __ldg(p5 + k) == b) {
            int e8 = __ldg(p8 + k);
            if ((e8 >> 5) == rank) {
                int c = e8 & 31;
                int j = atomicAdd(&colcnt[c], 1);
                if (j < CAP) {
                    colk[c * CAP + j]  = (k << 8) | __ldg(p7 + k);
                    colc6[c * CAP + j] = __ldg(p6 + k);
                }
            }
        }
    }
    asm volatile("cp.async.wait_group 0;\n" ::: "memory");
    __syncthreads();   // buckets + slices + gather rows visible

    // ---- D: winner resolution + correction values (pure smem) ----
    if (tid < 32 * CAP) {
        int c = tid / CAP, j = tid % CAP;
        int n = colcnt[c]; if (n > CAP) n = CAP;
        if (j < n) {
            int me = colk[c * CAP + j];
            bool win = true;
            for (int j2 = 0; j2 < n; j2++) {
                int oth = colk[c * CAP + j2];
                if (((oth ^ me) & 255) == 0 && oth > me) { win = false; break; }
            }
            if (win) {
                int d7 = me & 255, c6 = colc6[tid];
                float pb = p1t[d7 * 32 + c];
                colcv[0 * 384 + tid] = smem[OFF_P4T  + c6] - pb;
                colcv[1 * 384 + tid] = smem[OFF_P11T + c6] - pb;
                colcv[2 * 384 + tid] = smem[OFF_P14T + c6] - pb;
            } else {
                colcv[0 * 384 + tid] = 0.0f;
                colcv[1 * 384 + tid] = 0.0f;
                colcv[2 * 384 + tid] = 0.0f;
            }
        }
    }
    __syncthreads();   // p1t may now be overwritten by M

    // ---- thread mapping: 16 d-chunks x 32 e-columns ----
    const int dch = tid >> 5;      // 0..15 (16 d each)
    const int el  = tid & 31;

    float* McB = p1t + dch * 16 * 32 + el;     // own cells only
    float* P3B = p3t + dch * 16 * 32 + el;

    // ---- 3-stage chain, fully smem-resident ----
    for (int s = 0; s < 3; s++) {
        const float* Xin  = (s & 1) ? X1 : X0;
        float*       Xout = (s & 1) ? X0 : X1;

        float acc0 = 0.f, acc1 = 0.f, acc2 = 0.f, acc3 = 0.f;
        const float4* X4 = (const float4*)(Xin + dch * 16 * 4);

        if (s == 0) {
            #pragma unroll
            for (int i = 0; i < 16; i++) {
                float m = fmaf(P3B[i * 32], 0.975f, McB[i * 32]);
                McB[i * 32] = m;               // cache M in place
                float4 x = X4[i];              // 4 heads
                acc0 += x.x * m;  acc1 += x.y * m;
                acc2 += x.z * m;  acc3 += x.w * m;
            }
        } else {
            #pragma unroll
            for (int i = 0; i < 16; i++) {
                float m = McB[i * 32];
                float4 x = X4[i];
                acc0 += x.x * m;  acc1 += x.y * m;
                acc2 += x.z * m;  acc3 += x.w * m;
            }
        }

        // write partials: red[dch][h][el]
        red[(dch * 4 + 0) * 32 + el] = acc0;
        red[(dch * 4 + 1) * 32 + el] = acc1;
        red[(dch * 4 + 2) * 32 + el] = acc2;
        red[(dch * 4 + 3) * 32 + el] = acc3;
        __syncthreads();

        // reduce 16 partials + corrections + scale; push to all 8 CTAs
        if (tid < 128) {
            int h = tid >> 5, c = tid & 31;
            float sum = 0.0f;
            #pragma unroll
            for (int dc = 0; dc < 16; dc++) sum += red[(dc * 4 + h) * 32 + c];

            int n = colcnt[c]; if (n > CAP) n = CAP;
            for (int j = 0; j < n; j++) {
                int d7 = colk[c * CAP + j] & 255;
                sum += Xin[d7 * 4 + h] * colcv[s * 384 + c * CAP + j];
            }
            sum *= scal[s * 32 + c];

            if (s < 2) {
                float* dst = Xout + (e0 + c) * 4 + h;   // same offset in every CTA
                #pragma unroll
                for (int p = 0; p < CLUSTER; p++)
                    *cluster.map_shared_rank(dst, p) = sum;   // incl. self
            } else {
                out[(h0 + h) * 1536 + b * 256 + e0 + c] = sum;
            }
        }

        if (s < 2) cluster.sync();   // remote stores complete + full-CTA barrier
    }
}

extern "C" void kernel_launch(void* const* d_in, const int* in_sizes, int n_in,
                              void* d_out, int out_size)
{
    (void)n_in; (void)out_size;
    cudaFuncSetAttribute(chain_kernel,
                         cudaFuncAttributeMaxDynamicSharedMemorySize, SMEM_BYTES);
    chain_kernel<<<6 * 3 * CLUSTER, BLOCK, SMEM_BYTES>>>(
        (const float*)d_in[0],  (const float*)d_in[1],
        (const float*)d_in[2],  (const float*)d_in[3],
        (const int*)  d_in[4],  (const int*)  d_in[5],
        (const int*)  d_in[6],  (const int*)  d_in[7],
        (const float*)d_in[8],  (const float*)d_in[9],
        (const float*)d_in[10], (const float*)d_in[11],
        (const float*)d_in[12], (const float*)d_in[13],
        (const float*)d_in[14], (const float*)d_in[15],
        (float*)d_out, in_sizes[4]);
}

// round 16
// speedup vs baseline: 1.5088x; 1.5088x over previous
#include <cuda_runtime.h>
#include <cooperative_groups.h>
#include <cstdint>
#include <math.h>

namespace cg = cooperative_groups;

#define BLOCK 512
#define CLUSTER 4
#define CAP 12

// shared-memory layout (floats). Per CTA: 3 heads, 64 e-columns.
#define OFF_X0    0        // 1024  X buffer A: [d 0..255][4 (3 h + pad)]
#define OFF_X1    1024     // 1024  X buffer B
#define OFF_SCAL  2048     // 192   per-stage column scales [3][64]
#define OFF_CNT   2240     // 64    per-column bucket count (int)
#define OFF_COLK  2304     // 768   bucket packed (k<<8|d7) (int) [64][CAP]
#define OFF_COLC6 3072     // 768   bucket c6 (int) [64][CAP]
#define OFF_COLCV 3840     // 2304  correction values [3][64][CAP]
#define OFF_P4T   6144     // 256   p4 row for b
#define OFF_P11T  6400     // 256   p11 row for b
#define OFF_P14T  6656     // 256   p14 row for b
#define OFF_P1T   6912     // 16384 p1 slice [256 d][64 e]; becomes M in stage 0
#define OFF_P3T   23296    // 16384 p3 slice [256 d][64 e]
#define OFF_RED   39680    // 3072  partials [16 dch][3 h][64 e]
#define SMEM_FLOATS 42752
#define SMEM_BYTES (SMEM_FLOATS * 4)   // 171,008 B

extern __shared__ float smem[];

__device__ __forceinline__ void cp_async16(uint32_t saddr, const void* gptr) {
    asm volatile("cp.async.cg.shared.global [%0], [%1], 16;\n"
                 :: "r"(saddr), "l"(gptr));
}

__global__ void __cluster_dims__(CLUSTER, 1, 1) __launch_bounds__(BLOCK, 1)
chain_kernel(const float* __restrict__ p1, const float* __restrict__ p2,
             const float* __restrict__ p3, const float* __restrict__ p4,
             const int* __restrict__ p5, const int* __restrict__ p6,
             const int* __restrict__ p7, const int* __restrict__ p8,
             const float* __restrict__ p9, const float* __restrict__ p10,
             const float* __restrict__ p11, const float* __restrict__ p12,
             const float* __restrict__ p13, const float* __restrict__ p14,
             const float* __restrict__ p15, const float* __restrict__ p16,
             float* __restrict__ out, int K)
{
    cg::cluster_group cluster = cg::this_cluster();
    const int tid  = (int)threadIdx.x;
    const int rank = (int)cluster.block_rank();   // e-segment 0..3
    const int cid  = (int)blockIdx.x >> 2;        // 0..23
    const int b    = cid >> 2;                    // batch 0..5
    const int h0   = (cid & 3) * 3;               // head-group base (3 heads)
    const int e0   = rank * 64;

    float* X0     = smem + OFF_X0;
    float* X1     = smem + OFF_X1;
    float* scal   = smem + OFF_SCAL;
    float* colcv  = smem + OFF_COLCV;
    float* p1t    = smem + OFF_P1T;
    float* p3t    = smem + OFF_P3T;
    float* red    = smem + OFF_RED;
    int*   colcnt = (int*)(smem + OFF_CNT);
    int*   colk   = (int*)(smem + OFF_COLK);
    int*   colc6  = (int*)(smem + OFF_COLC6);

    const int KC = (K < 2048) ? K : 2048;

    // ---- A: cp.async burst: p1/p3 64-col slices + gather rows ----
    {
        uint32_t sb = (uint32_t)__cvta_generic_to_shared(smem);
        const float* g1 = p1 + b * 65536 + e0;
        const float* g3 = p3 + b * 65536 + e0;
        #pragma unroll
        for (int it = 0; it < 8; it++) {
            int idx = tid + it * BLOCK;          // 0..4095
            int row = idx >> 4, q = (idx & 15) << 2;
            cp_async16(sb + (OFF_P1T + row * 64 + q) * 4, g1 + row * 256 + q);
            cp_async16(sb + (OFF_P3T + row * 64 + q) * 4, g3 + row * 256 + q);
        }
        if (tid < 192) {
            int a = tid / 64, c = (tid % 64) << 2;
            const float* gs = (a == 0) ? p4 : (a == 1) ? p11 : p14;
            cp_async16(sb + (OFF_P4T + a * 256 + c) * 4, gs + b * 256 + c);
        }
        asm volatile("cp.async.commit_group;\n" ::: "memory");
    }

    // ---- B: counters, X0 transpose-load (3 heads), mod scales ----
    if (tid < 64) colcnt[tid] = 0;

    for (int i = tid; i < 768; i += BLOCK) {      // 2 iters
        int h = i >> 8, d = i & 255;
        X0[d * 4 + h] = p2[(h0 + h) * 1536 + b * 256 + d];
    }

    if (tid < 64) {
        float fr[3] = { p9[0],  p12[0], p15[0] };
        float ph[3] = { p10[0], p13[0], p16[0] };
        float t = (float)(e0 + tid);
        #pragma unroll
        for (int s = 0; s < 3; s++) {
            float a  = t * 6.2831853071795864f;
            a = a * fr[s] + ph[s];
            float sv = sinf(a);
            float m  = sv * sv * 0.1f + 0.95f;
            scal[s * 64 + tid] = (s == 1) ? m : (1.0f / m);
        }
    }
    __syncthreads();   // counters + X0 visible before scan

    // ---- C: scan from GLOBAL -> per-column buckets ----
    #pragma unroll
    for (int it = 0; it < 4; it++) {
        int k = tid + it * BLOCK;
        if (k < KC && __ldg(p5 + k) == b) {
            int e8 = __ldg(p8 + k);
            if ((e8 >> 6) == rank) {
                int c = e8 & 63;
                int j = atomicAdd(&colcnt[c], 1);
                if (j < CAP) {
                    colk[c * CAP + j]  = (k << 8) | __ldg(p7 + k);
                    colc6[c * CAP + j] = __ldg(p6 + k);
                }
            }
        }
    }
    asm volatile("cp.async.wait_group 0;\n" ::: "memory");
    __syncthreads();   // buckets + slices + gather rows visible

    // ---- D: winner resolution + correction values (pure smem) ----
    for (int o = tid; o < 64 * CAP; o += BLOCK) {   // 2 iters
        int c = o / CAP, j = o % CAP;
        int n = colcnt[c]; if (n > CAP) n = CAP;
        if (j < n) {
            int me = colk[c * CAP + j];
            bool win = true;
            for (int j2 = 0; j2 < n; j2++) {
                int oth = colk[c * CAP + j2];
                if (((oth ^ me) & 255) == 0 && oth > me) { win = false; break; }
            }
            if (win) {
                int d7 = me & 255, c6 = colc6[o];
                float pb = p1t[d7 * 64 + c];
                colcv[0 * 768 + o] = smem[OFF_P4T  + c6] - pb;
                colcv[1 * 768 + o] = smem[OFF_P11T + c6] - pb;
                colcv[2 * 768 + o] = smem[OFF_P14T + c6] - pb;
            } else {
                colcv[0 * 768 + o] = 0.0f;
                colcv[1 * 768 + o] = 0.0f;
                colcv[2 * 768 + o] = 0.0f;
            }
        }
    }
    __syncthreads();   // p1t may now be overwritten by M

    // ---- thread mapping: 16 d-chunks x 32 column-pairs ----
    const int dch = tid >> 5;      // 0..15 (16 d each)
    const int el2 = (tid & 31) * 2;

    float* McB = p1t + dch * 16 * 64 + el2;    // own cells only
    float* P3B = p3t + dch * 16 * 64 + el2;

    // ---- 3-stage chain, fully smem-resident ----
    for (int s = 0; s < 3; s++) {
        const float* Xin  = (s & 1) ? X1 : X0;
        float*       Xout = (s & 1) ? X0 : X1;

        float a00 = 0.f, a01 = 0.f, a10 = 0.f, a11 = 0.f, a20 = 0.f, a21 = 0.f;
        const float4* X4 = (const float4*)(Xin + dch * 16 * 4);

        if (s == 0) {
            #pragma unroll
            for (int i = 0; i < 16; i++) {
                float2 p1v = *(const float2*)(McB + i * 64);
                float2 p3v = *(const float2*)(P3B + i * 64);
                float mx = fmaf(p3v.x, 0.975f, p1v.x);
                float my = fmaf(p3v.y, 0.975f, p1v.y);
                *(float2*)(McB + i * 64) = make_float2(mx, my);
                float4 x = X4[i];              // 3 heads (+pad)
                a00 += x.x * mx;  a01 += x.x * my;
                a10 += x.y * mx;  a11 += x.y * my;
                a20 += x.z * mx;  a21 += x.z * my;
            }
        } else {
            #pragma unroll
            for (int i = 0; i < 16; i++) {
                float2 m = *(const float2*)(McB + i * 64);
                float4 x = X4[i];
                a00 += x.x * m.x;  a01 += x.x * m.y;
                a10 += x.y * m.x;  a11 += x.y * m.y;
                a20 += x.z * m.x;  a21 += x.z * m.y;
            }
        }

        // write partials: red[dch][h][e]
        *(float2*)&red[(dch * 3 + 0) * 64 + el2] = make_float2(a00, a01);
        *(float2*)&red[(dch * 3 + 1) * 64 + el2] = make_float2(a10, a11);
        *(float2*)&red[(dch * 3 + 2) * 64 + el2] = make_float2(a20, a21);
        __syncthreads();

        // reduce 16 partials + corrections + scale; push to all 4 CTAs
        if (tid < 192) {
            int h = tid >> 6, c = tid & 63;
            float sum = 0.0f;
            #pragma unroll
            for (int dc = 0; dc < 16; dc++) sum += red[(dc * 3 + h) * 64 + c];

            int n = colcnt[c]; if (n > CAP) n = CAP;
            for (int j = 0; j < n; j++) {
                int d7 = colk[c * CAP + j] & 255;
                sum += Xin[d7 * 4 + h] * colcv[s * 768 + c * CAP + j];
            }
            sum *= scal[s * 64 + c];

            if (s < 2) {
                float* dst = Xout + (e0 + c) * 4 + h;   // same offset in every CTA
                #pragma unroll
                for (int p = 0; p < CLUSTER; p++)
                    *cluster.map_shared_rank(dst, p) = sum;   // incl. self
            } else {
                out[(h0 + h) * 1536 + b * 256 + e0 + c] = sum;
            }
        }

        if (s < 2) cluster.sync();   // remote stores complete + full-CTA barrier
    }
}

extern "C" void kernel_launch(void* const* d_in, const int* in_sizes, int n_in,
                              void* d_out, int out_size)
{
    (void)n_in; (void)out_size;
    cudaFuncSetAttribute(chain_kernel,
                         cudaFuncAttributeMaxDynamicSharedMemorySize, SMEM_BYTES);
    chain_kernel<<<6 * 4 * CLUSTER, BLOCK, SMEM_BYTES>>>(
        (const float*)d_in[0],  (const float*)d_in[1],
        (const float*)d_in[2],  (const float*)d_in[3],
        (const int*)  d_in[4],  (const int*)  d_in[5],
        (const int*)  d_in[6],  (const int*)  d_in[7],
        (const float*)d_in[8],  (const float*)d_in[9],
        (const float*)d_in[10], (const float*)d_in[11],
        (const float*)d_in[12], (const float*)d_in[13],
        (const float*)d_in[14], (const float*)d_in[15],
        (float*)d_out, in_sizes[4]);
}